// round 12
// baseline (speedup 1.0000x reference)
#include <cuda_runtime.h>
#include <cuda_bf16.h>
#include <math.h>
#include <stdint.h>

// ============================================================================
// SAE forward: encoder GEMM as bf16x3 split on mma.sync HMMA (dedup hi segs,
// K physical 1536, 36 virtual chunks); histogram fused into GEMM epilogue;
// single-scan top-k; sparse decode + losses.
// ============================================================================

#define BATCH 1024
#define DM 768
#define NF 32768
#define TOPK 64
#define AUXK 128
#define DEAD_AFTER 1000
#define AUX_COEFF 0.03125f

#define KB 1536            // physical K: [hi(768) | lo(768)]

// ---------------- scratch (device globals; no allocation allowed) -----------
__device__ float g_xn[BATCH * DM];
__device__ __align__(128) __nv_bfloat16 g_As[BATCH * KB];            // 3.1 MB
__device__ __align__(128) __nv_bfloat16 g_Bs[(size_t)NF * KB];       // 100 MB
__device__ float g_enc[(size_t)BATCH * NF];                          // 134 MB
__device__ unsigned g_dmask[NF / 32];
__device__ unsigned g_hist[(size_t)BATCH * 2048];                    // 8 MB
__device__ float g_w[BATCH * TOPK];
__device__ int   g_idx[BATCH * TOPK];
__device__ float g_aw[BATCH * AUXK];
__device__ int   g_aidx[BATCH * AUXK];
__device__ float g_recon[BATCH];
__device__ float g_auxl[BATCH];
__device__ float g_rowxn2[BATCH];

__device__ __forceinline__ unsigned fkey(float f)
{
    unsigned u = __float_as_uint(f);
    return u ^ (((unsigned)((int)u >> 31)) | 0x80000000u);
}

// ---------------- kernel 1: normalize + pre-bias + A split ------------------
__global__ void prep_kernel(const float* __restrict__ x,
                            const float* __restrict__ b_pre,
                            const float* __restrict__ b_post,
                            const float* __restrict__ avg_norm)
{
    int i = blockIdx.x * 256 + threadIdx.x;          // BATCH*DM total, exact
    float s = sqrtf((float)DM) / avg_norm[0];
    int d = i % DM;
    int m = i / DM;
    float v = x[i] * s;
    g_xn[i] = v;
    float p = v - b_post[d] + b_pre[d];
    __nv_bfloat16 hi = __float2bfloat16(p);
    __nv_bfloat16 lo = __float2bfloat16(p - __bfloat162float(hi));
    g_As[(size_t)m * KB + d]       = hi;
    g_As[(size_t)m * KB + DM + d]  = lo;
}

// ---------------- kernel 1b: W_enc transpose + bf16 split -------------------
__global__ void bsplit_kernel(const float* __restrict__ W)
{
    __shared__ float t[32][33];
    int n0 = blockIdx.x * 32;
    int k0 = blockIdx.y * 32;
    int tx = threadIdx.x & 31;
    int ty = threadIdx.x >> 5;   // 0..7
#pragma unroll
    for (int r = 0; r < 4; r++)
        t[ty + r * 8][tx] = W[(size_t)(k0 + ty + r * 8) * NF + n0 + tx];
    __syncthreads();
#pragma unroll
    for (int r = 0; r < 4; r++) {
        int n = n0 + ty + r * 8;
        int k = k0 + tx;
        float v = t[tx][ty + r * 8];
        __nv_bfloat16 hi = __float2bfloat16(v);
        __nv_bfloat16 lo = __float2bfloat16(v - __bfloat162float(hi));
        size_t base = (size_t)n * KB;
        g_Bs[base + k]       = hi;
        g_Bs[base + DM + k]  = lo;
    }
}

// ---------------- kernel 1c: dead bitmask + hist zero ------------------------
__global__ void dmask_kernel(const int* __restrict__ act)
{
    int i = blockIdx.x * 256 + threadIdx.x;
    unsigned b = __ballot_sync(0xffffffffu, act[i] > DEAD_AFTER);
    if ((threadIdx.x & 31) == 0) g_dmask[i >> 5] = b;
}

__global__ void hzero_kernel()
{
    g_hist[(size_t)blockIdx.x * 1024 + threadIdx.x] = 0;
}

// ---------------- kernel 2: bf16 mma.sync GEMM ------------------------------
// Virtual K = 2304 over 36 chunks of 64; A terms [hi|hi|lo], B [hi|lo|hi]
#define BM 128
#define BN 128
#define BK 64
#define NCHUNK 36
#define STAGEB (BM * BK * 2 + BN * BK * 2)   // 32768 bytes
#define NSTAGE 3
#define GEMM_SMEM (NSTAGE * STAGEB)          // 98304

__device__ __forceinline__ int srcA_off(int ci)
{
    int c = (ci < 12) ? ci : (ci < 24 ? ci - 12 : ci - 24);
    return ((ci >= 24) ? DM : 0) + c * BK;       // hi, hi, lo
}
__device__ __forceinline__ int srcB_off(int ci)
{
    int c = (ci < 12) ? ci : (ci < 24 ? ci - 12 : ci - 24);
    return ((ci >= 12 && ci < 24) ? DM : 0) + c * BK;  // hi, lo, hi
}

__device__ __forceinline__ uint32_t s2u(const void* p)
{
    uint32_t a;
    asm("{ .reg .u64 t; cvta.to.shared.u64 t, %1; cvt.u32.u64 %0, t; }" : "=r"(a) : "l"(p));
    return a;
}

__device__ __forceinline__ void cpa16(uint32_t dst, const void* src)
{
    asm volatile("cp.async.cg.shared.global [%0], [%1], 16;" :: "r"(dst), "l"(src) : "memory");
}

__device__ __forceinline__ void ldsm4(uint32_t& r0, uint32_t& r1, uint32_t& r2, uint32_t& r3,
                                      uint32_t addr)
{
    asm volatile("ldmatrix.sync.aligned.m8n8.x4.shared.b16 {%0,%1,%2,%3}, [%4];"
                 : "=r"(r0), "=r"(r1), "=r"(r2), "=r"(r3) : "r"(addr));
}

__device__ __forceinline__ void mma16816(float* c, const uint32_t* a, const uint32_t* b)
{
    asm volatile("mma.sync.aligned.m16n8k16.row.col.f32.bf16.bf16.f32 "
                 "{%0,%1,%2,%3}, {%4,%5,%6,%7}, {%8,%9}, {%0,%1,%2,%3};"
                 : "+f"(c[0]), "+f"(c[1]), "+f"(c[2]), "+f"(c[3])
                 : "r"(a[0]), "r"(a[1]), "r"(a[2]), "r"(a[3]), "r"(b[0]), "r"(b[1]));
}

__global__ void __launch_bounds__(256, 2) gemm_kernel()
{
    extern __shared__ char smem[];
    const uint32_t sbase = s2u(smem);
    const int tid = threadIdx.x;
    const int wid = tid >> 5;
    const int lid = tid & 31;
    const int m0 = blockIdx.x * BM;
    const int n0 = blockIdx.y * BN;
    const int wm = (wid >> 2) * 64;
    const int wn = (wid & 3) * 32;

    const __nv_bfloat16* Ab = g_As + (size_t)m0 * KB;
    const __nv_bfloat16* Bb = g_Bs + (size_t)n0 * KB;

    const int lr = tid >> 3;
    const int lc = tid & 7;
    const uint32_t lcol = lc * 16;

    auto load_chunk = [&](int ci, int st) {
        uint32_t s0 = sbase + st * STAGEB;
        const __nv_bfloat16* ap = Ab + srcA_off(ci) + lc * 8;
        const __nv_bfloat16* bp = Bb + srcB_off(ci) + lc * 8;
#pragma unroll
        for (int j = 0; j < 4; j++) {
            int r = lr + j * 32;
            uint32_t sw = r * 128 + (lcol ^ ((r << 4) & 0x70));
            cpa16(s0 + sw, ap + (size_t)r * KB);
        }
#pragma unroll
        for (int j = 0; j < 4; j++) {
            int r = lr + j * 32;
            uint32_t sw = r * 128 + (lcol ^ ((r << 4) & 0x70));
            cpa16(s0 + 16384 + sw, bp + (size_t)r * KB);
        }
        asm volatile("cp.async.commit_group;" ::: "memory");
    };

    const int g = lid >> 3;
    const int r8 = lid & 7;
    uint32_t aRow[4], aXor[4];
#pragma unroll
    for (int mt = 0; mt < 4; mt++) {
        int row = wm + mt * 16 + (g & 1) * 8 + r8;
        aRow[mt] = row * 128;
        aXor[mt] = (row << 4) & 0x70;
    }
    const uint32_t aColG = (g >> 1) * 16;
    uint32_t bRow[2], bXor[2];
#pragma unroll
    for (int ng = 0; ng < 2; ng++) {
        int row = wn + ng * 16 + (g >> 1) * 8 + r8;
        bRow[ng] = row * 128;
        bXor[ng] = (row << 4) & 0x70;
    }
    const uint32_t bColG = (g & 1) * 16;

    float acc[4][4][4];
#pragma unroll
    for (int i = 0; i < 4; i++)
#pragma unroll
        for (int j = 0; j < 4; j++)
#pragma unroll
            for (int q = 0; q < 4; q++) acc[i][j][q] = 0.0f;

    load_chunk(0, 0);
    load_chunk(1, 1);

    for (int i = 0; i < NCHUNK; i++) {
        __syncthreads();
        if (i + 2 < NCHUNK) load_chunk(i + 2, (i + 2) % NSTAGE);
        asm volatile("cp.async.wait_group 2;" ::: "memory");
        __syncthreads();

        uint32_t sb = sbase + (i % NSTAGE) * STAGEB;
        uint32_t sbB = sb + 16384;
#pragma unroll
        for (int ks = 0; ks < 4; ks++) {
            uint32_t kbyte = ks * 32;
            uint32_t aF[4][4];
#pragma unroll
            for (int mt = 0; mt < 4; mt++)
                ldsm4(aF[mt][0], aF[mt][1], aF[mt][2], aF[mt][3],
                      sb + aRow[mt] + ((kbyte + aColG) ^ aXor[mt]));
            uint32_t bF[4][2];
#pragma unroll
            for (int ng = 0; ng < 2; ng++) {
                uint32_t q0, q1, q2, q3;
                ldsm4(q0, q1, q2, q3, sbB + bRow[ng] + ((kbyte + bColG) ^ bXor[ng]));
                bF[2 * ng][0] = q0; bF[2 * ng][1] = q1;
                bF[2 * ng + 1][0] = q2; bF[2 * ng + 1][1] = q3;
            }
#pragma unroll
            for (int mt = 0; mt < 4; mt++)
#pragma unroll
                for (int nt = 0; nt < 4; nt++)
                    mma16816(acc[mt][nt], aF[mt], bF[nt]);
        }
    }

    // ---- epilogue: write C + fused row histogram (counts | dead<<16) ----
    const int erow = lid >> 2;
    const int ecol = (lid & 3) * 2;
#pragma unroll
    for (int mt = 0; mt < 4; mt++) {
        int m = m0 + wm + mt * 16 + erow;
        float* base = g_enc + (size_t)m * NF + n0 + wn + ecol;
        unsigned* h0 = g_hist + (size_t)m * 2048;
        unsigned* h1 = g_hist + (size_t)(m + 8) * 2048;
#pragma unroll
        for (int nt = 0; nt < 4; nt++) {
            *(float2*)(base + nt * 8) = make_float2(acc[mt][nt][0], acc[mt][nt][1]);
            *(float2*)(base + (size_t)8 * NF + nt * 8) = make_float2(acc[mt][nt][2], acc[mt][nt][3]);
            int c0 = n0 + wn + ecol + nt * 8;
            unsigned d0 = ((g_dmask[c0 >> 5] >> (c0 & 31)) & 1u) << 16;
            unsigned d1 = ((g_dmask[c0 >> 5] >> ((c0 + 1) & 31)) & 1u) << 16;
            atomicAdd(&h0[fkey(acc[mt][nt][0]) >> 21], 1u + d0);
            atomicAdd(&h0[fkey(acc[mt][nt][1]) >> 21], 1u + d1);
            atomicAdd(&h1[fkey(acc[mt][nt][2]) >> 21], 1u + d0);
            atomicAdd(&h1[fkey(acc[mt][nt][3]) >> 21], 1u + d1);
        }
    }
}

// ---------------- kernel 3: single-scan top-k (hist precomputed) -------------
#define MCAP 2048

__global__ void __launch_bounds__(1024) topk_kernel()
{
    __shared__ unsigned hist[2048];      // total | dead<<16
    __shared__ unsigned sg[64];          // 32-bin group sums (packed)
    __shared__ float candv[MCAP];
    __shared__ int   candi[MCAP];
    __shared__ float acandv[MCAP];
    __shared__ int   acandi[MCAP];
    __shared__ unsigned s_cm_out, s_cm_cand, s_ca_out, s_ca_cand;
    __shared__ int s_tbm, s_cgtm, s_tba, s_cgta, s_asel;

    const int row = blockIdx.x;
    const int tid = threadIdx.x;
    const float4* enc4 = (const float4*)(g_enc + (size_t)row * NF);
    const unsigned* hrow = g_hist + (size_t)row * 2048;

    hist[tid] = hrow[tid];
    hist[tid + 1024] = hrow[tid + 1024];
    if (tid == 0) { s_cm_out = 0; s_cm_cand = 0; s_ca_out = 0; s_ca_cand = 0; }
    __syncthreads();

    // ---- group sums ----
    if (tid < 64) {
        unsigned s = 0;
#pragma unroll 8
        for (int b = 0; b < 32; b++) s += hist[tid * 32 + b];
        sg[tid] = s;
    }
    __syncthreads();

    // ---- threshold search: main by thread 0, aux by thread 32 ----
    if (tid == 0) {
        unsigned cum = 0; int g = 63;
        for (; g > 0; g--) {
            unsigned c = sg[g] & 0xFFFFu;
            if (cum + c >= (unsigned)TOPK) break;
            cum += c;
        }
        int b = g * 32 + 31;
        for (; b > g * 32; b--) {
            unsigned c = hist[b] & 0xFFFFu;
            if (cum + c >= (unsigned)TOPK) break;
            cum += c;
        }
        s_tbm = b; s_cgtm = (int)cum;
    } else if (tid == 32) {
        unsigned nd = 0;
        for (int g2 = 0; g2 < 64; g2++) nd += sg[g2] >> 16;
        int asel = nd < (unsigned)AUXK ? (int)nd : AUXK;
        s_asel = asel;
        if (asel > 0) {
            unsigned cum = 0; int g = 63;
            for (; g > 0; g--) {
                unsigned c = sg[g] >> 16;
                if (cum + c >= (unsigned)asel) break;
                cum += c;
            }
            int b = g * 32 + 31;
            for (; b > g * 32; b--) {
                unsigned c = hist[b] >> 16;
                if (cum + c >= (unsigned)asel) break;
                cum += c;
            }
            s_tba = b; s_cgta = (int)cum;
        } else { s_tba = 0x7FFFFFFF; s_cgta = 0; }
    }
    __syncthreads();

    const int tbm = s_tbm;
    const int tba = s_tba;
    const int asel = s_asel;
    float* rowW = g_w + row * TOPK;
    int*   rowI = g_idx + row * TOPK;
    float* rowAW = g_aw + row * AUXK;
    int*   rowAI = g_aidx + row * AUXK;

    // ---- gather scan ----
    for (int i4 = tid; i4 < NF / 4; i4 += 1024) {
        float4 v = enc4[i4];
        unsigned bits = (g_dmask[i4 >> 3] >> ((i4 & 7) * 4)) & 0xFu;
        int i = i4 * 4;
#pragma unroll
        for (int j = 0; j < 4; j++) {
            float val = (j == 0) ? v.x : (j == 1) ? v.y : (j == 2) ? v.z : v.w;
            int bin = (int)(fkey(val) >> 21);
            if (bin >= tbm) {
                if (bin > tbm) {
                    unsigned p = atomicAdd(&s_cm_out, 1u);
                    rowW[p] = val; rowI[p] = i + j;
                } else {
                    unsigned p = atomicAdd(&s_cm_cand, 1u);
                    if (p < MCAP) { candv[p] = val; candi[p] = i + j; }
                }
            }
            if ((bits >> j) & 1u) {
                if (bin >= tba) {
                    if (bin > tba) {
                        unsigned p = atomicAdd(&s_ca_out, 1u);
                        rowAW[p] = val; rowAI[p] = i + j;
                    } else {
                        unsigned p = atomicAdd(&s_ca_cand, 1u);
                        if (p < MCAP) { acandv[p] = val; acandi[p] = i + j; }
                    }
                }
            }
        }
    }
    __syncthreads();

    // ---- refinement: warp 0 = main, warp 1 = aux, rest zero-fill aux tail ----
    const int wid = tid >> 5;
    const int lane = tid & 31;
    if (wid == 0) {
        int nc = min((int)s_cm_cand, MCAP);
        int kr = TOPK - s_cgtm;
        int base = s_cgtm;
        for (int s = 0; s < kr; s++) {
            float bv = -3.4e38f; int bp = 0;
            for (int j = lane; j < nc; j += 32) {
                float v = candv[j];
                if (v > bv) { bv = v; bp = j; }
            }
#pragma unroll
            for (int o = 16; o; o >>= 1) {
                float ov = __shfl_xor_sync(0xffffffffu, bv, o);
                int op = __shfl_xor_sync(0xffffffffu, bp, o);
                if (ov > bv) { bv = ov; bp = op; }
            }
            if (lane == 0) {
                rowW[base + s] = bv; rowI[base + s] = candi[bp];
                candv[bp] = -3.4e38f;
            }
            __syncwarp();
        }
    } else if (wid == 1) {
        if (asel > 0) {
            int nc = min((int)s_ca_cand, MCAP);
            int kr = asel - s_cgta;
            int base = s_cgta;
            for (int s = 0; s < kr; s++) {
                float bv = -3.4e38f; int bp = 0;
                for (int j = lane; j < nc; j += 32) {
                    float v = acandv[j];
                    if (v > bv) { bv = v; bp = j; }
                }
#pragma unroll
                for (int o = 16; o; o >>= 1) {
                    float ov = __shfl_xor_sync(0xffffffffu, bv, o);
                    int op = __shfl_xor_sync(0xffffffffu, bp, o);
                    if (ov > bv) { bv = ov; bp = op; }
                }
                if (lane == 0) {
                    rowAW[base + s] = bv; rowAI[base + s] = acandi[bp];
                    acandv[bp] = -3.4e38f;
                }
                __syncwarp();
            }
        }
    } else {
        for (int p = asel + (tid - 64); p < AUXK; p += 1024 - 64) {
            rowAW[p] = 0.0f; rowAI[p] = 0;
        }
    }
}

// ---------------- kernel 4: sparse decode + per-row losses -------------------
__global__ void decode_kernel(const float* __restrict__ W_dec,
                              const float* __restrict__ b_post,
                              const float* __restrict__ avg_norm,
                              float* __restrict__ out)
{
    const int row = blockIdx.x;
    const int tid = threadIdx.x;   // 256 threads, 3 d-elements each

    __shared__ float sw[TOPK];
    __shared__ int   sidx[TOPK];
    __shared__ float saw[AUXK];
    __shared__ int   said[AUXK];
    __shared__ float red[256];

    if (tid < TOPK)  { sw[tid] = g_w[row * TOPK + tid];  sidx[tid] = g_idx[row * TOPK + tid]; }
    if (tid < AUXK)  { saw[tid] = g_aw[row * AUXK + tid]; said[tid] = g_aidx[row * AUXK + tid]; }
    __syncthreads();

    float acc0 = 0.f, acc1 = 0.f, acc2 = 0.f;
#pragma unroll 4
    for (int k = 0; k < TOPK; k++) {
        const float* r = W_dec + (size_t)sidx[k] * DM;
        float wk = sw[k];
        acc0 += wk * r[tid];
        acc1 += wk * r[tid + 256];
        acc2 += wk * r[tid + 512];
    }
    float a0 = 0.f, a1 = 0.f, a2 = 0.f;
#pragma unroll 4
    for (int k = 0; k < AUXK; k++) {
        const float* r = W_dec + (size_t)said[k] * DM;
        float wk = saw[k];
        a0 += wk * r[tid];
        a1 += wk * r[tid + 256];
        a2 += wk * r[tid + 512];
    }

    float bp0 = b_post[tid], bp1 = b_post[tid + 256], bp2 = b_post[tid + 512];
    float yn0 = acc0 + bp0, yn1 = acc1 + bp1, yn2 = acc2 + bp2;
    float x0 = g_xn[row * DM + tid];
    float x1 = g_xn[row * DM + tid + 256];
    float x2 = g_xn[row * DM + tid + 512];

    float d0 = x0 - yn0, d1 = x1 - yn1, d2 = x2 - yn2;
    float e0 = yn0 - x0 - a0, e1 = yn1 - x1 - a1, e2 = yn2 - x2 - a2;

    float rsum, asum, xsum;
    red[tid] = d0 * d0 + d1 * d1 + d2 * d2; __syncthreads();
    for (int s = 128; s > 0; s >>= 1) { if (tid < s) red[tid] += red[tid + s]; __syncthreads(); }
    rsum = red[0]; __syncthreads();
    red[tid] = e0 * e0 + e1 * e1 + e2 * e2; __syncthreads();
    for (int s = 128; s > 0; s >>= 1) { if (tid < s) red[tid] += red[tid + s]; __syncthreads(); }
    asum = red[0]; __syncthreads();
    red[tid] = x0 * x0 + x1 * x1 + x2 * x2; __syncthreads();
    for (int s = 128; s > 0; s >>= 1) { if (tid < s) red[tid] += red[tid + s]; __syncthreads(); }
    xsum = red[0]; __syncthreads();

    float yscale = avg_norm[0] / sqrtf((float)DM);
    out[row * DM + tid]       = yn0 * yscale;
    out[row * DM + tid + 256] = yn1 * yscale;
    out[row * DM + tid + 512] = yn2 * yscale;

    if (tid == 0) {
        g_recon[row] = rsum / (float)DM;
        g_auxl[row] = asum / (float)DM;
        g_rowxn2[row] = xsum;
    }
}

// ---------------- kernel 5: finalize loss + fvu ------------------------------
__global__ void finalize_kernel(const int* __restrict__ act, float* __restrict__ out)
{
    const int tid = threadIdx.x;   // 1024 threads, 1 block
    __shared__ float red[1024];
    __shared__ int s_flag;
    if (tid == 0) s_flag = 0;
    __syncthreads();

    int any = 0;
    for (int i = tid; i < NF; i += 1024) any |= (act[i] > DEAD_AFTER);
    if (any) atomicOr(&s_flag, 1);

    red[tid] = g_recon[tid]; __syncthreads();
    for (int s = 512; s > 0; s >>= 1) { if (tid < s) red[tid] += red[tid + s]; __syncthreads(); }
    float sumr = red[0]; __syncthreads();
    red[tid] = g_rowxn2[tid]; __syncthreads();
    for (int s = 512; s > 0; s >>= 1) { if (tid < s) red[tid] += red[tid + s]; __syncthreads(); }
    float sumx = red[0]; __syncthreads();

    float auxc = s_flag ? AUX_COEFF : 0.0f;
    out[BATCH * DM + tid] = g_recon[tid] + auxc * g_auxl[tid];
    if (tid == 0)
        out[BATCH * DM + BATCH] = sumr * (float)DM / sumx;   // fvu
}

// ---------------- launch -----------------------------------------------------
extern "C" void kernel_launch(void* const* d_in, const int* in_sizes, int n_in,
                              void* d_out, int out_size)
{
    const float* x        = (const float*)d_in[0];
    const float* W_enc    = (const float*)d_in[1];
    const float* W_dec    = (const float*)d_in[2];
    const float* b_pre    = (const float*)d_in[3];
    const float* b_post   = (const float*)d_in[4];
    const float* avg_norm = (const float*)d_in[5];
    const int*   act      = (const int*)d_in[6];
    float* out = (float*)d_out;

    cudaFuncSetAttribute(gemm_kernel, cudaFuncAttributeMaxDynamicSharedMemorySize, GEMM_SMEM);

    prep_kernel<<<(BATCH * DM) / 256, 256>>>(x, b_pre, b_post, avg_norm);
    bsplit_kernel<<<dim3(NF / 32, DM / 32), 256>>>(W_enc);
    dmask_kernel<<<NF / 256, 256>>>(act);
    hzero_kernel<<<BATCH * 2, 1024>>>();
    gemm_kernel<<<dim3(BATCH / BM, NF / BN), 256, GEMM_SMEM>>>();
    topk_kernel<<<BATCH, 1024>>>();
    decode_kernel<<<BATCH, 256>>>(W_dec, b_post, avg_norm, out);
    finalize_kernel<<<1, 1024>>>(act, out);
}

// round 15
// speedup vs baseline: 1.1302x; 1.1302x over previous
#include <cuda_runtime.h>
#include <cuda_bf16.h>
#include <math.h>
#include <stdint.h>

// ============================================================================
// SAE forward: encoder GEMM as bf16x3 split on mma.sync HMMA (dedup hi segs,
// physical K=1536, 36 virtual chunks); two-scan histogram top-k; sparse
// decode + losses.
// ============================================================================

#define BATCH 1024
#define DM 768
#define NF 32768
#define TOPK 64
#define AUXK 128
#define DEAD_AFTER 1000
#define AUX_COEFF 0.03125f

#define KB 1536            // physical K: [hi(768) | lo(768)]

// ---------------- scratch (device globals; no allocation allowed) -----------
__device__ float g_xn[BATCH * DM];
__device__ __align__(128) __nv_bfloat16 g_As[BATCH * KB];            // 3.1 MB
__device__ __align__(128) __nv_bfloat16 g_Bs[(size_t)NF * KB];       // 100 MB
__device__ float g_enc[(size_t)BATCH * NF];                          // 134 MB
__device__ unsigned g_dmask[NF / 32];
__device__ float g_w[BATCH * TOPK];
__device__ int   g_idx[BATCH * TOPK];
__device__ float g_aw[BATCH * AUXK];
__device__ int   g_aidx[BATCH * AUXK];
__device__ float g_recon[BATCH];
__device__ float g_auxl[BATCH];
__device__ float g_rowxn2[BATCH];

__device__ __forceinline__ unsigned fkey(float f)
{
    unsigned u = __float_as_uint(f);
    return u ^ (((unsigned)((int)u >> 31)) | 0x80000000u);
}

// ---------------- kernel 1: normalize + pre-bias + A split ------------------
__global__ void prep_kernel(const float* __restrict__ x,
                            const float* __restrict__ b_pre,
                            const float* __restrict__ b_post,
                            const float* __restrict__ avg_norm)
{
    int i = blockIdx.x * 256 + threadIdx.x;          // BATCH*DM total, exact
    float s = sqrtf((float)DM) / avg_norm[0];
    int d = i % DM;
    int m = i / DM;
    float v = x[i] * s;
    g_xn[i] = v;
    float p = v - b_post[d] + b_pre[d];
    __nv_bfloat16 hi = __float2bfloat16(p);
    __nv_bfloat16 lo = __float2bfloat16(p - __bfloat162float(hi));
    g_As[(size_t)m * KB + d]       = hi;
    g_As[(size_t)m * KB + DM + d]  = lo;
}

// ---------------- kernel 1b: W_enc transpose + bf16 split -------------------
__global__ void bsplit_kernel(const float* __restrict__ W)
{
    __shared__ float t[32][33];
    int n0 = blockIdx.x * 32;
    int k0 = blockIdx.y * 32;
    int tx = threadIdx.x & 31;
    int ty = threadIdx.x >> 5;   // 0..7
#pragma unroll
    for (int r = 0; r < 4; r++)
        t[ty + r * 8][tx] = W[(size_t)(k0 + ty + r * 8) * NF + n0 + tx];
    __syncthreads();
#pragma unroll
    for (int r = 0; r < 4; r++) {
        int n = n0 + ty + r * 8;
        int k = k0 + tx;
        float v = t[tx][ty + r * 8];
        __nv_bfloat16 hi = __float2bfloat16(v);
        __nv_bfloat16 lo = __float2bfloat16(v - __bfloat162float(hi));
        size_t base = (size_t)n * KB;
        g_Bs[base + k]       = hi;
        g_Bs[base + DM + k]  = lo;
    }
}

// ---------------- kernel 1c: dead bitmask (once) -----------------------------
__global__ void dmask_kernel(const int* __restrict__ act)
{
    int i = blockIdx.x * 256 + threadIdx.x;
    unsigned b = __ballot_sync(0xffffffffu, act[i] > DEAD_AFTER);
    if ((threadIdx.x & 31) == 0) g_dmask[i >> 5] = b;
}

// ---------------- kernel 2: bf16 mma.sync GEMM ------------------------------
// Virtual K = 2304 over 36 chunks of 64; A terms [hi|hi|lo], B [hi|lo|hi]
#define BM 128
#define BN 128
#define BK 64
#define NCHUNK 36
#define STAGEB (BM * BK * 2 + BN * BK * 2)   // 32768 bytes
#define NSTAGE 3
#define GEMM_SMEM (NSTAGE * STAGEB)          // 98304

__device__ __forceinline__ int srcA_off(int ci)
{
    int c = (ci < 12) ? ci : (ci < 24 ? ci - 12 : ci - 24);
    return ((ci >= 24) ? DM : 0) + c * BK;       // hi, hi, lo
}
__device__ __forceinline__ int srcB_off(int ci)
{
    int c = (ci < 12) ? ci : (ci < 24 ? ci - 12 : ci - 24);
    return ((ci >= 12 && ci < 24) ? DM : 0) + c * BK;  // hi, lo, hi
}

__device__ __forceinline__ uint32_t s2u(const void* p)
{
    uint32_t a;
    asm("{ .reg .u64 t; cvta.to.shared.u64 t, %1; cvt.u32.u64 %0, t; }" : "=r"(a) : "l"(p));
    return a;
}

__device__ __forceinline__ void cpa16(uint32_t dst, const void* src)
{
    asm volatile("cp.async.cg.shared.global [%0], [%1], 16;" :: "r"(dst), "l"(src) : "memory");
}

__device__ __forceinline__ void ldsm4(uint32_t& r0, uint32_t& r1, uint32_t& r2, uint32_t& r3,
                                      uint32_t addr)
{
    asm volatile("ldmatrix.sync.aligned.m8n8.x4.shared.b16 {%0,%1,%2,%3}, [%4];"
                 : "=r"(r0), "=r"(r1), "=r"(r2), "=r"(r3) : "r"(addr));
}

__device__ __forceinline__ void mma16816(float* c, const uint32_t* a, const uint32_t* b)
{
    asm volatile("mma.sync.aligned.m16n8k16.row.col.f32.bf16.bf16.f32 "
                 "{%0,%1,%2,%3}, {%4,%5,%6,%7}, {%8,%9}, {%0,%1,%2,%3};"
                 : "+f"(c[0]), "+f"(c[1]), "+f"(c[2]), "+f"(c[3])
                 : "r"(a[0]), "r"(a[1]), "r"(a[2]), "r"(a[3]), "r"(b[0]), "r"(b[1]));
}

__global__ void __launch_bounds__(256, 2) gemm_kernel()
{
    extern __shared__ char smem[];
    const uint32_t sbase = s2u(smem);
    const int tid = threadIdx.x;
    const int wid = tid >> 5;
    const int lid = tid & 31;
    const int m0 = blockIdx.x * BM;
    const int n0 = blockIdx.y * BN;
    const int wm = (wid >> 2) * 64;
    const int wn = (wid & 3) * 32;

    const __nv_bfloat16* Ab = g_As + (size_t)m0 * KB;
    const __nv_bfloat16* Bb = g_Bs + (size_t)n0 * KB;

    const int lr = tid >> 3;
    const int lc = tid & 7;
    const uint32_t lcol = lc * 16;

    auto load_chunk = [&](int ci, int st) {
        uint32_t s0 = sbase + st * STAGEB;
        const __nv_bfloat16* ap = Ab + srcA_off(ci) + lc * 8;
        const __nv_bfloat16* bp = Bb + srcB_off(ci) + lc * 8;
#pragma unroll
        for (int j = 0; j < 4; j++) {
            int r = lr + j * 32;
            uint32_t sw = r * 128 + (lcol ^ ((r << 4) & 0x70));
            cpa16(s0 + sw, ap + (size_t)r * KB);
        }
#pragma unroll
        for (int j = 0; j < 4; j++) {
            int r = lr + j * 32;
            uint32_t sw = r * 128 + (lcol ^ ((r << 4) & 0x70));
            cpa16(s0 + 16384 + sw, bp + (size_t)r * KB);
        }
        asm volatile("cp.async.commit_group;" ::: "memory");
    };

    const int g = lid >> 3;
    const int r8 = lid & 7;
    uint32_t aRow[4], aXor[4];
#pragma unroll
    for (int mt = 0; mt < 4; mt++) {
        int row = wm + mt * 16 + (g & 1) * 8 + r8;
        aRow[mt] = row * 128;
        aXor[mt] = (row << 4) & 0x70;
    }
    const uint32_t aColG = (g >> 1) * 16;
    uint32_t bRow[2], bXor[2];
#pragma unroll
    for (int ng = 0; ng < 2; ng++) {
        int row = wn + ng * 16 + (g >> 1) * 8 + r8;
        bRow[ng] = row * 128;
        bXor[ng] = (row << 4) & 0x70;
    }
    const uint32_t bColG = (g & 1) * 16;

    float acc[4][4][4];
#pragma unroll
    for (int i = 0; i < 4; i++)
#pragma unroll
        for (int j = 0; j < 4; j++)
#pragma unroll
            for (int q = 0; q < 4; q++) acc[i][j][q] = 0.0f;

    load_chunk(0, 0);
    load_chunk(1, 1);

    for (int i = 0; i < NCHUNK; i++) {
        __syncthreads();
        if (i + 2 < NCHUNK) load_chunk(i + 2, (i + 2) % NSTAGE);
        asm volatile("cp.async.wait_group 2;" ::: "memory");
        __syncthreads();

        uint32_t sb = sbase + (i % NSTAGE) * STAGEB;
        uint32_t sbB = sb + 16384;
#pragma unroll
        for (int ks = 0; ks < 4; ks++) {
            uint32_t kbyte = ks * 32;
            uint32_t aF[4][4];
#pragma unroll
            for (int mt = 0; mt < 4; mt++)
                ldsm4(aF[mt][0], aF[mt][1], aF[mt][2], aF[mt][3],
                      sb + aRow[mt] + ((kbyte + aColG) ^ aXor[mt]));
            uint32_t bF[4][2];
#pragma unroll
            for (int ng = 0; ng < 2; ng++) {
                uint32_t q0, q1, q2, q3;
                ldsm4(q0, q1, q2, q3, sbB + bRow[ng] + ((kbyte + bColG) ^ bXor[ng]));
                bF[2 * ng][0] = q0; bF[2 * ng][1] = q1;
                bF[2 * ng + 1][0] = q2; bF[2 * ng + 1][1] = q3;
            }
#pragma unroll
            for (int mt = 0; mt < 4; mt++)
#pragma unroll
                for (int nt = 0; nt < 4; nt++)
                    mma16816(acc[mt][nt], aF[mt], bF[nt]);
        }
    }

    const int erow = lid >> 2;
    const int ecol = (lid & 3) * 2;
#pragma unroll
    for (int mt = 0; mt < 4; mt++) {
        int m = m0 + wm + mt * 16 + erow;
        float* base = g_enc + (size_t)m * NF + n0 + wn + ecol;
#pragma unroll
        for (int nt = 0; nt < 4; nt++) {
            *(float2*)(base + nt * 8) = make_float2(acc[mt][nt][0], acc[mt][nt][1]);
            *(float2*)(base + (size_t)8 * NF + nt * 8) = make_float2(acc[mt][nt][2], acc[mt][nt][3]);
        }
    }
}

// ---------------- kernel 3: two-scan histogram top-k -------------------------
#define MCAP 2048

__global__ void __launch_bounds__(1024) topk_kernel()
{
    __shared__ unsigned hist[2048];      // total | dead<<16
    __shared__ unsigned sg[64];          // 32-bin group sums (packed)
    __shared__ float candv[MCAP];
    __shared__ int   candi[MCAP];
    __shared__ float acandv[MCAP];
    __shared__ int   acandi[MCAP];
    __shared__ unsigned s_cm_out, s_cm_cand, s_ca_out, s_ca_cand;
    __shared__ int s_tbm, s_cgtm, s_tba, s_cgta, s_asel;

    const int row = blockIdx.x;
    const int tid = threadIdx.x;
    const float4* enc4 = (const float4*)(g_enc + (size_t)row * NF);

    hist[tid] = 0; hist[tid + 1024] = 0;
    if (tid == 0) { s_cm_out = 0; s_cm_cand = 0; s_ca_out = 0; s_ca_cand = 0; }
    __syncthreads();

    // ---- scan 1: packed histogram ----
    for (int i4 = tid; i4 < NF / 4; i4 += 1024) {
        float4 v = enc4[i4];
        unsigned bits = (g_dmask[i4 >> 3] >> ((i4 & 7) * 4)) & 0xFu;
        atomicAdd(&hist[fkey(v.x) >> 21], 1u | ((bits & 1u) << 16));
        atomicAdd(&hist[fkey(v.y) >> 21], 1u | ((bits & 2u) << 15));
        atomicAdd(&hist[fkey(v.z) >> 21], 1u | ((bits & 4u) << 14));
        atomicAdd(&hist[fkey(v.w) >> 21], 1u | ((bits & 8u) << 13));
    }
    __syncthreads();

    // ---- group sums ----
    if (tid < 64) {
        unsigned s = 0;
#pragma unroll 8
        for (int b = 0; b < 32; b++) s += hist[tid * 32 + b];
        sg[tid] = s;
    }
    __syncthreads();

    // ---- threshold search: main by thread 0, aux by thread 32 ----
    if (tid == 0) {
        unsigned cum = 0; int g = 63;
        for (; g > 0; g--) {
            unsigned c = sg[g] & 0xFFFFu;
            if (cum + c >= (unsigned)TOPK) break;
            cum += c;
        }
        int b = g * 32 + 31;
        for (; b > g * 32; b--) {
            unsigned c = hist[b] & 0xFFFFu;
            if (cum + c >= (unsigned)TOPK) break;
            cum += c;
        }
        s_tbm = b; s_cgtm = (int)cum;
    } else if (tid == 32) {
        unsigned nd = 0;
        for (int g2 = 0; g2 < 64; g2++) nd += sg[g2] >> 16;
        int asel = nd < (unsigned)AUXK ? (int)nd : AUXK;
        s_asel = asel;
        if (asel > 0) {
            unsigned cum = 0; int g = 63;
            for (; g > 0; g--) {
                unsigned c = sg[g] >> 16;
                if (cum + c >= (unsigned)asel) break;
                cum += c;
            }
            int b = g * 32 + 31;
            for (; b > g * 32; b--) {
                unsigned c = hist[b] >> 16;
                if (cum + c >= (unsigned)asel) break;
                cum += c;
            }
            s_tba = b; s_cgta = (int)cum;
        } else { s_tba = 0x7FFFFFFF; s_cgta = 0; }
    }
    __syncthreads();

    const int tbm = s_tbm;
    const int tba = s_tba;
    const int asel = s_asel;
    float* rowW = g_w + row * TOPK;
    int*   rowI = g_idx + row * TOPK;
    float* rowAW = g_aw + row * AUXK;
    int*   rowAI = g_aidx + row * AUXK;

    // ---- scan 2: gather ----
    for (int i4 = tid; i4 < NF / 4; i4 += 1024) {
        float4 v = enc4[i4];
        unsigned bits = (g_dmask[i4 >> 3] >> ((i4 & 7) * 4)) & 0xFu;
        int i = i4 * 4;
#pragma unroll
        for (int j = 0; j < 4; j++) {
            float val = (j == 0) ? v.x : (j == 1) ? v.y : (j == 2) ? v.z : v.w;
            int bin = (int)(fkey(val) >> 21);
            if (bin >= tbm) {
                if (bin > tbm) {
                    unsigned p = atomicAdd(&s_cm_out, 1u);
                    rowW[p] = val; rowI[p] = i + j;
                } else {
                    unsigned p = atomicAdd(&s_cm_cand, 1u);
                    if (p < MCAP) { candv[p] = val; candi[p] = i + j; }
                }
            }
            if ((bits >> j) & 1u) {
                if (bin >= tba) {
                    if (bin > tba) {
                        unsigned p = atomicAdd(&s_ca_out, 1u);
                        rowAW[p] = val; rowAI[p] = i + j;
                    } else {
                        unsigned p = atomicAdd(&s_ca_cand, 1u);
                        if (p < MCAP) { acandv[p] = val; acandi[p] = i + j; }
                    }
                }
            }
        }
    }
    __syncthreads();

    // ---- refinement: warp 0 = main, warp 1 = aux, rest zero-fill aux tail ----
    const int wid = tid >> 5;
    const int lane = tid & 31;
    if (wid == 0) {
        int nc = min((int)s_cm_cand, MCAP);
        int kr = TOPK - s_cgtm;
        int base = s_cgtm;
        for (int s = 0; s < kr; s++) {
            float bv = -3.4e38f; int bp = 0;
            for (int j = lane; j < nc; j += 32) {
                float v = candv[j];
                if (v > bv) { bv = v; bp = j; }
            }
#pragma unroll
            for (int o = 16; o; o >>= 1) {
                float ov = __shfl_xor_sync(0xffffffffu, bv, o);
                int op = __shfl_xor_sync(0xffffffffu, bp, o);
                if (ov > bv) { bv = ov; bp = op; }
            }
            if (lane == 0) {
                rowW[base + s] = bv; rowI[base + s] = candi[bp];
                candv[bp] = -3.4e38f;
            }
            __syncwarp();
        }
    } else if (wid == 1) {
        if (asel > 0) {
            int nc = min((int)s_ca_cand, MCAP);
            int kr = asel - s_cgta;
            int base = s_cgta;
            for (int s = 0; s < kr; s++) {
                float bv = -3.4e38f; int bp = 0;
                for (int j = lane; j < nc; j += 32) {
                    float v = acandv[j];
                    if (v > bv) { bv = v; bp = j; }
                }
#pragma unroll
                for (int o = 16; o; o >>= 1) {
                    float ov = __shfl_xor_sync(0xffffffffu, bv, o);
                    int op = __shfl_xor_sync(0xffffffffu, bp, o);
                    if (ov > bv) { bv = ov; bp = op; }
                }
                if (lane == 0) {
                    rowAW[base + s] = bv; rowAI[base + s] = acandi[bp];
                    acandv[bp] = -3.4e38f;
                }
                __syncwarp();
            }
        }
    } else {
        for (int p = asel + (tid - 64); p < AUXK; p += 1024 - 64) {
            rowAW[p] = 0.0f; rowAI[p] = 0;
        }
    }
}

// ---------------- kernel 4: sparse decode + per-row losses -------------------
__global__ void decode_kernel(const float* __restrict__ W_dec,
                              const float* __restrict__ b_post,
                              const float* __restrict__ avg_norm,
                              float* __restrict__ out)
{
    const int row = blockIdx.x;
    const int tid = threadIdx.x;   // 256 threads, 3 d-elements each

    __shared__ float sw[TOPK];
    __shared__ int   sidx[TOPK];
    __shared__ float saw[AUXK];
    __shared__ int   said[AUXK];
    __shared__ float red[256];

    if (tid < TOPK)  { sw[tid] = g_w[row * TOPK + tid];  sidx[tid] = g_idx[row * TOPK + tid]; }
    if (tid < AUXK)  { saw[tid] = g_aw[row * AUXK + tid]; said[tid] = g_aidx[row * AUXK + tid]; }
    __syncthreads();

    float acc0 = 0.f, acc1 = 0.f, acc2 = 0.f;
#pragma unroll 4
    for (int k = 0; k < TOPK; k++) {
        const float* r = W_dec + (size_t)sidx[k] * DM;
        float wk = sw[k];
        acc0 += wk * r[tid];
        acc1 += wk * r[tid + 256];
        acc2 += wk * r[tid + 512];
    }
    float a0 = 0.f, a1 = 0.f, a2 = 0.f;
#pragma unroll 4
    for (int k = 0; k < AUXK; k++) {
        const float* r = W_dec + (size_t)said[k] * DM;
        float wk = saw[k];
        a0 += wk * r[tid];
        a1 += wk * r[tid + 256];
        a2 += wk * r[tid + 512];
    }

    float bp0 = b_post[tid], bp1 = b_post[tid + 256], bp2 = b_post[tid + 512];
    float yn0 = acc0 + bp0, yn1 = acc1 + bp1, yn2 = acc2 + bp2;
    float x0 = g_xn[row * DM + tid];
    float x1 = g_xn[row * DM + tid + 256];
    float x2 = g_xn[row * DM + tid + 512];

    float d0 = x0 - yn0, d1 = x1 - yn1, d2 = x2 - yn2;
    float e0 = yn0 - x0 - a0, e1 = yn1 - x1 - a1, e2 = yn2 - x2 - a2;

    float rsum, asum, xsum;
    red[tid] = d0 * d0 + d1 * d1 + d2 * d2; __syncthreads();
    for (int s = 128; s > 0; s >>= 1) { if (tid < s) red[tid] += red[tid + s]; __syncthreads(); }
    rsum = red[0]; __syncthreads();
    red[tid] = e0 * e0 + e1 * e1 + e2 * e2; __syncthreads();
    for (int s = 128; s > 0; s >>= 1) { if (tid < s) red[tid] += red[tid + s]; __syncthreads(); }
    asum = red[0]; __syncthreads();
    red[tid] = x0 * x0 + x1 * x1 + x2 * x2; __syncthreads();
    for (int s = 128; s > 0; s >>= 1) { if (tid < s) red[tid] += red[tid + s]; __syncthreads(); }
    xsum = red[0]; __syncthreads();

    float yscale = avg_norm[0] / sqrtf((float)DM);
    out[row * DM + tid]       = yn0 * yscale;
    out[row * DM + tid + 256] = yn1 * yscale;
    out[row * DM + tid + 512] = yn2 * yscale;

    if (tid == 0) {
        g_recon[row] = rsum / (float)DM;
        g_auxl[row] = asum / (float)DM;
        g_rowxn2[row] = xsum;
    }
}

// ---------------- kernel 5: finalize loss + fvu ------------------------------
__global__ void finalize_kernel(const int* __restrict__ act, float* __restrict__ out)
{
    const int tid = threadIdx.x;   // 1024 threads, 1 block
    __shared__ float red[1024];
    __shared__ int s_flag;
    if (tid == 0) s_flag = 0;
    __syncthreads();

    int any = 0;
    for (int i = tid; i < NF; i += 1024) any |= (act[i] > DEAD_AFTER);
    if (any) atomicOr(&s_flag, 1);

    red[tid] = g_recon[tid]; __syncthreads();
    for (int s = 512; s > 0; s >>= 1) { if (tid < s) red[tid] += red[tid + s]; __syncthreads(); }
    float sumr = red[0]; __syncthreads();
    red[tid] = g_rowxn2[tid]; __syncthreads();
    for (int s = 512; s > 0; s >>= 1) { if (tid < s) red[tid] += red[tid + s]; __syncthreads(); }
    float sumx = red[0]; __syncthreads();

    float auxc = s_flag ? AUX_COEFF : 0.0f;
    out[BATCH * DM + tid] = g_recon[tid] + auxc * g_auxl[tid];
    if (tid == 0)
        out[BATCH * DM + BATCH] = sumr * (float)DM / sumx;   // fvu
}

// ---------------- launch -----------------------------------------------------
extern "C" void kernel_launch(void* const* d_in, const int* in_sizes, int n_in,
                              void* d_out, int out_size)
{
    const float* x        = (const float*)d_in[0];
    const float* W_enc    = (const float*)d_in[1];
    const float* W_dec    = (const float*)d_in[2];
    const float* b_pre    = (const float*)d_in[3];
    const float* b_post   = (const float*)d_in[4];
    const float* avg_norm = (const float*)d_in[5];
    const int*   act      = (const int*)d_in[6];
    float* out = (float*)d_out;

    cudaFuncSetAttribute(gemm_kernel, cudaFuncAttributeMaxDynamicSharedMemorySize, GEMM_SMEM);

    prep_kernel<<<(BATCH * DM) / 256, 256>>>(x, b_pre, b_post, avg_norm);
    bsplit_kernel<<<dim3(NF / 32, DM / 32), 256>>>(W_enc);
    dmask_kernel<<<NF / 256, 256>>>(act);
    gemm_kernel<<<dim3(BATCH / BM, NF / BN), 256, GEMM_SMEM>>>();
    topk_kernel<<<BATCH, 1024>>>();
    decode_kernel<<<BATCH, 256>>>(W_dec, b_post, avg_norm, out);
    finalize_kernel<<<1, 1024>>>(act, out);
}